// round 1
// baseline (speedup 1.0000x reference)
#include <cuda_runtime.h>

#define NSEQ   384
#define CDIM   128
#define NROWS  (NSEQ*NSEQ)          /* 147456 */
#define LN_EPS 1e-5f

/* ------------------------------------------------------------------ */
/* Scratch (device globals; no allocation in kernel_launch)            */
/* ------------------------------------------------------------------ */
__device__ float g_x [(size_t)NROWS*CDIM];   /* LN(z)                       */
__device__ float g_at[(size_t)CDIM*NROWS];   /* a, layout [c][i*N+k]        */
__device__ float g_bt[(size_t)CDIM*NROWS];   /* b, layout [c][j*N+k]        */
__device__ float g_gs[(size_t)NROWS*CDIM];   /* sigmoid(x@w_g+b_g), [r][c]  */
__device__ float g_tt[(size_t)CDIM*NROWS];   /* t, layout [c][i*N+j]        */
__device__ float g_y [(size_t)NROWS*CDIM];   /* LN_out(t), [r][c]           */
__device__ float g_wcat[CDIM*640];           /* interleaved weights [k][n]  */
__device__ float g_bcat[640];

__device__ __forceinline__ float sigm(float x){ return 1.f/(1.f+__expf(-x)); }
__device__ __forceinline__ float f2tf(float f){
    unsigned u; asm("cvt.rna.tf32.f32 %0, %1;" : "=r"(u) : "f"(f));
    return __uint_as_float(u);
}

#define MMA_TF32(d,a,b) asm volatile( \
    "mma.sync.aligned.m16n8k8.row.col.f32.tf32.tf32.f32 " \
    "{%0,%1,%2,%3},{%4,%5,%6,%7},{%8,%9},{%0,%1,%2,%3};" \
    : "+f"(d[0]),"+f"(d[1]),"+f"(d[2]),"+f"(d[3]) \
    : "r"(a[0]),"r"(a[1]),"r"(a[2]),"r"(a[3]),"r"(b[0]),"r"(b[1]))

/* ------------------------------------------------------------------ */
/* K0: build interleaved weight/bias concat                            */
/*   cols 0..255 : (w_a_p[:,t], w_a_g[:,t]) interleaved                */
/*   cols 256..511: (w_b_p, w_b_g) interleaved                         */
/*   cols 512..639: w_g                                                */
/* ------------------------------------------------------------------ */
__global__ void k_build(const float* __restrict__ wap, const float* __restrict__ wag,
                        const float* __restrict__ wbp, const float* __restrict__ wbg,
                        const float* __restrict__ wg,
                        const float* __restrict__ bap, const float* __restrict__ bag,
                        const float* __restrict__ bbp, const float* __restrict__ bbg,
                        const float* __restrict__ bg)
{
    int id = blockIdx.x*blockDim.x + threadIdx.x;
    if (id >= CDIM*640) return;
    int k = id/640, col = id%640;
    float v;
    if (col < 256)      { int t = col>>1;        v = (col&1) ? wag[k*CDIM+t] : wap[k*CDIM+t]; }
    else if (col < 512) { int t = (col-256)>>1;  v = (col&1) ? wbg[k*CDIM+t] : wbp[k*CDIM+t]; }
    else                {                        v = wg[k*CDIM + (col-512)]; }
    g_wcat[id] = v;
    if (k == 0) {
        float b;
        if (col < 256)      { int t = col>>1;       b = (col&1) ? bag[t] : bap[t]; }
        else if (col < 512) { int t = (col-256)>>1; b = (col&1) ? bbg[t] : bbp[t]; }
        else                {                       b = bg[col-512]; }
        g_bcat[col] = b;
    }
}

/* ------------------------------------------------------------------ */
/* K1: input LayerNorm, one warp per row                               */
/* ------------------------------------------------------------------ */
__global__ void k_ln_in(const float* __restrict__ z,
                        const float* __restrict__ w, const float* __restrict__ b)
{
    int warp = threadIdx.x>>5, lane = threadIdx.x&31;
    size_t row = (size_t)blockIdx.x*8 + warp;
    float4 v = ((const float4*)(z + row*CDIM))[lane];
    float s = v.x+v.y+v.z+v.w;
    #pragma unroll
    for (int o=16;o;o>>=1) s += __shfl_xor_sync(~0u, s, o);
    float mu = s*(1.f/128.f);
    float dx=v.x-mu, dy=v.y-mu, dz=v.z-mu, dw=v.w-mu;
    float q = dx*dx+dy*dy+dz*dz+dw*dw;
    #pragma unroll
    for (int o=16;o;o>>=1) q += __shfl_xor_sync(~0u, q, o);
    float rs = rsqrtf(q*(1.f/128.f) + LN_EPS);
    float4 wv = ((const float4*)w)[lane];
    float4 bv = ((const float4*)b)[lane];
    float4 o4;
    o4.x = dx*rs*wv.x + bv.x;  o4.y = dy*rs*wv.y + bv.y;
    o4.z = dz*rs*wv.z + bv.z;  o4.w = dw*rs*wv.w + bv.w;
    ((float4*)(g_x + row*CDIM))[lane] = o4;
}

/* ------------------------------------------------------------------ */
/* K2: fused projection GEMM  X[147456x128] @ Wcat[128x640]            */
/*   BM=128 BN=128 BK=32, 8 warps (2m x 4n), tf32 mma                  */
/*   epilogue: register-level sigmoid gating, transposed a/b stores    */
/* ------------------------------------------------------------------ */
__global__ __launch_bounds__(256) void k_gemm1(const float* __restrict__ mask)
{
    __shared__ float Ash[128][33];   /* [m][k] */
    __shared__ float Bsh[128][33];   /* [n][k] */
    const int tid = threadIdx.x;
    const int warp = tid>>5, lane = tid&31;
    const int wm = warp & 1, wn = warp >> 1;
    const int tr = lane>>2, tc = lane&3;
    const int nb = blockIdx.x;
    const size_t m0 = (size_t)blockIdx.y*128;
    const int n0 = nb*128;

    float acc[4][4][4];
    #pragma unroll
    for (int i=0;i<4;i++)
        #pragma unroll
        for (int j=0;j<4;j++)
            #pragma unroll
            for (int r=0;r<4;r++) acc[i][j][r]=0.f;

    for (int k0=0;k0<128;k0+=32){
        #pragma unroll
        for (int it=0; it<4; it++){
            int r  = (tid>>3) + it*32;
            int c4 = (tid&7)*4;
            float4 v = *(const float4*)(g_x + (m0+r)*CDIM + k0 + c4);
            Ash[r][c4+0]=f2tf(v.x); Ash[r][c4+1]=f2tf(v.y);
            Ash[r][c4+2]=f2tf(v.z); Ash[r][c4+3]=f2tf(v.w);
        }
        #pragma unroll
        for (int it=0; it<4; it++){
            int kr = (tid>>5) + it*8;
            int c4 = (tid&31)*4;
            float4 v = *(const float4*)(g_wcat + (k0+kr)*640 + n0 + c4);
            Bsh[c4+0][kr]=f2tf(v.x); Bsh[c4+1][kr]=f2tf(v.y);
            Bsh[c4+2][kr]=f2tf(v.z); Bsh[c4+3][kr]=f2tf(v.w);
        }
        __syncthreads();
        #pragma unroll
        for (int kk=0;kk<4;kk++){
            unsigned af[4][4], bf[4][2];
            #pragma unroll
            for (int mi=0;mi<4;mi++){
                int row = wm*64 + mi*16 + tr;
                af[mi][0]=__float_as_uint(Ash[row  ][kk*8+tc  ]);
                af[mi][1]=__float_as_uint(Ash[row+8][kk*8+tc  ]);
                af[mi][2]=__float_as_uint(Ash[row  ][kk*8+tc+4]);
                af[mi][3]=__float_as_uint(Ash[row+8][kk*8+tc+4]);
            }
            #pragma unroll
            for (int ni=0;ni<4;ni++){
                int col = wn*32 + ni*8 + tr;
                bf[ni][0]=__float_as_uint(Bsh[col][kk*8+tc  ]);
                bf[ni][1]=__float_as_uint(Bsh[col][kk*8+tc+4]);
            }
            #pragma unroll
            for (int mi=0;mi<4;mi++)
                #pragma unroll
                for (int ni=0;ni<4;ni++)
                    MMA_TF32(acc[mi][ni], af[mi], bf[ni]);
        }
        __syncthreads();
    }

    #pragma unroll
    for (int mi=0;mi<4;mi++){
        size_t r1 = m0 + (size_t)(wm*64 + mi*16 + tr);
        size_t r2 = r1 + 8;
        float mk1 = mask[r1], mk2 = mask[r2];
        #pragma unroll
        for (int ni=0;ni<4;ni++){
            int gcol = n0 + wn*32 + ni*8 + 2*tc;
            float b0 = g_bcat[gcol], b1 = g_bcat[gcol+1];
            float c0 = acc[mi][ni][0]+b0, c1 = acc[mi][ni][1]+b1;
            float c2 = acc[mi][ni][2]+b0, c3 = acc[mi][ni][3]+b1;
            if (nb < 2){                       /* a = m*sig(g)*p, transposed */
                size_t ch = (size_t)(gcol>>1);
                g_at[ch*NROWS + r1] = mk1*sigm(c1)*c0;
                g_at[ch*NROWS + r2] = mk2*sigm(c3)*c2;
            } else if (nb < 4){
                size_t ch = (size_t)((gcol>>1) - 128);
                g_bt[ch*NROWS + r1] = mk1*sigm(c1)*c0;
                g_bt[ch*NROWS + r2] = mk2*sigm(c3)*c2;
            } else {                           /* gate, row-major */
                int gc = gcol - 512;
                g_gs[r1*CDIM+gc  ]=sigm(c0); g_gs[r1*CDIM+gc+1]=sigm(c1);
                g_gs[r2*CDIM+gc  ]=sigm(c2); g_gs[r2*CDIM+gc+1]=sigm(c3);
            }
        }
    }
}

/* ------------------------------------------------------------------ */
/* K3: channel-batched einsum  T_c = A_c @ B_c^T  (384x384x384, c=z)   */
/* ------------------------------------------------------------------ */
__global__ __launch_bounds__(256) void k_gemm2()
{
    __shared__ float Ash[128][33];   /* [i][k] */
    __shared__ float Bsh[128][33];   /* [j][k] */
    const int tid = threadIdx.x;
    const int warp = tid>>5, lane = tid&31;
    const int wm = warp & 1, wn = warp >> 1;
    const int tr = lane>>2, tc = lane&3;
    const size_t plane = (size_t)blockIdx.z*NROWS;
    const float* __restrict__ A = g_at + plane;
    const float* __restrict__ B = g_bt + plane;
    const int m0 = blockIdx.y*128, n0 = blockIdx.x*128;

    float acc[4][4][4];
    #pragma unroll
    for (int i=0;i<4;i++)
        #pragma unroll
        for (int j=0;j<4;j++)
            #pragma unroll
            for (int r=0;r<4;r++) acc[i][j][r]=0.f;

    for (int k0=0;k0<NSEQ;k0+=32){
        #pragma unroll
        for (int it=0; it<4; it++){
            int r  = (tid>>3) + it*32;
            int c4 = (tid&7)*4;
            float4 va = *(const float4*)(A + (size_t)(m0+r)*NSEQ + k0 + c4);
            Ash[r][c4+0]=f2tf(va.x); Ash[r][c4+1]=f2tf(va.y);
            Ash[r][c4+2]=f2tf(va.z); Ash[r][c4+3]=f2tf(va.w);
            float4 vb = *(const float4*)(B + (size_t)(n0+r)*NSEQ + k0 + c4);
            Bsh[r][c4+0]=f2tf(vb.x); Bsh[r][c4+1]=f2tf(vb.y);
            Bsh[r][c4+2]=f2tf(vb.z); Bsh[r][c4+3]=f2tf(vb.w);
        }
        __syncthreads();
        #pragma unroll
        for (int kk=0;kk<4;kk++){
            unsigned af[4][4], bf[4][2];
            #pragma unroll
            for (int mi=0;mi<4;mi++){
                int row = wm*64 + mi*16 + tr;
                af[mi][0]=__float_as_uint(Ash[row  ][kk*8+tc  ]);
                af[mi][1]=__float_as_uint(Ash[row+8][kk*8+tc  ]);
                af[mi][2]=__float_as_uint(Ash[row  ][kk*8+tc+4]);
                af[mi][3]=__float_as_uint(Ash[row+8][kk*8+tc+4]);
            }
            #pragma unroll
            for (int ni=0;ni<4;ni++){
                int col = wn*32 + ni*8 + tr;
                bf[ni][0]=__float_as_uint(Bsh[col][kk*8+tc  ]);
                bf[ni][1]=__float_as_uint(Bsh[col][kk*8+tc+4]);
            }
            #pragma unroll
            for (int mi=0;mi<4;mi++)
                #pragma unroll
                for (int ni=0;ni<4;ni++)
                    MMA_TF32(acc[mi][ni], af[mi], bf[ni]);
        }
        __syncthreads();
    }

    #pragma unroll
    for (int mi=0;mi<4;mi++){
        size_t i1 = (size_t)(m0 + wm*64 + mi*16 + tr);
        size_t i2 = i1 + 8;
        #pragma unroll
        for (int ni=0;ni<4;ni++){
            int j = n0 + wn*32 + ni*8 + 2*tc;
            *(float2*)(g_tt + plane + i1*NSEQ + j) = make_float2(acc[mi][ni][0], acc[mi][ni][1]);
            *(float2*)(g_tt + plane + i2*NSEQ + j) = make_float2(acc[mi][ni][2], acc[mi][ni][3]);
        }
    }
}

/* ------------------------------------------------------------------ */
/* K4: gather t over channel planes + output LayerNorm -> g_y [r][c]   */
/* ------------------------------------------------------------------ */
__global__ void k_gather(const float* __restrict__ lw, const float* __restrict__ lb)
{
    __shared__ float sh[128][33];    /* [c][r] */
    const int tid = threadIdx.x;
    const size_t r0 = (size_t)blockIdx.x*32;
    #pragma unroll
    for (int it=0;it<16;it++){
        int idx = it*256 + tid;
        int c = idx>>5, r = idx&31;
        sh[c][r] = g_tt[(size_t)c*NROWS + r0 + r];
    }
    __syncthreads();
    const int warp = tid>>5, lane = tid&31;
    #pragma unroll
    for (int rr=0;rr<4;rr++){
        int r = warp*4 + rr;
        float v0=sh[lane][r], v1=sh[lane+32][r], v2=sh[lane+64][r], v3=sh[lane+96][r];
        float s = v0+v1+v2+v3;
        #pragma unroll
        for (int o=16;o;o>>=1) s += __shfl_xor_sync(~0u, s, o);
        float mu = s*(1.f/128.f);
        float d0=v0-mu,d1=v1-mu,d2=v2-mu,d3=v3-mu;
        float q = d0*d0+d1*d1+d2*d2+d3*d3;
        #pragma unroll
        for (int o=16;o;o>>=1) q += __shfl_xor_sync(~0u, q, o);
        float rs = rsqrtf(q*(1.f/128.f) + LN_EPS);
        float* yr = g_y + (r0+r)*CDIM;
        yr[lane   ] = d0*rs*lw[lane   ] + lb[lane   ];
        yr[lane+32] = d1*rs*lw[lane+32] + lb[lane+32];
        yr[lane+64] = d2*rs*lw[lane+64] + lb[lane+64];
        yr[lane+96] = d3*rs*lw[lane+96] + lb[lane+96];
    }
}

/* ------------------------------------------------------------------ */
/* K5: output GEMM  y[147456x128] @ w_o[128x128] + b_o, times gate     */
/* ------------------------------------------------------------------ */
__global__ __launch_bounds__(256) void k_gemm3(const float* __restrict__ wo,
                                               const float* __restrict__ bo,
                                               float* __restrict__ out)
{
    __shared__ float Ash[128][33];
    __shared__ float Bsh[128][33];   /* [n][k] */
    const int tid = threadIdx.x;
    const int warp = tid>>5, lane = tid&31;
    const int wm = warp & 1, wn = warp >> 1;
    const int tr = lane>>2, tc = lane&3;
    const size_t m0 = (size_t)blockIdx.x*128;

    float acc[4][4][4];
    #pragma unroll
    for (int i=0;i<4;i++)
        #pragma unroll
        for (int j=0;j<4;j++)
            #pragma unroll
            for (int r=0;r<4;r++) acc[i][j][r]=0.f;

    for (int k0=0;k0<128;k0+=32){
        #pragma unroll
        for (int it=0; it<4; it++){
            int r  = (tid>>3) + it*32;
            int c4 = (tid&7)*4;
            float4 v = *(const float4*)(g_y + (m0+r)*CDIM + k0 + c4);
            Ash[r][c4+0]=f2tf(v.x); Ash[r][c4+1]=f2tf(v.y);
            Ash[r][c4+2]=f2tf(v.z); Ash[r][c4+3]=f2tf(v.w);
        }
        #pragma unroll
        for (int it=0; it<4; it++){
            int kr = (tid>>5) + it*8;
            int c4 = (tid&31)*4;
            float4 v = *(const float4*)(wo + (k0+kr)*CDIM + c4);
            Bsh[c4+0][kr]=f2tf(v.x); Bsh[c4+1][kr]=f2tf(v.y);
            Bsh[c4+2][kr]=f2tf(v.z); Bsh[c4+3][kr]=f2tf(v.w);
        }
        __syncthreads();
        #pragma unroll
        for (int kk=0;kk<4;kk++){
            unsigned af[4][4], bf[4][2];
            #pragma unroll
            for (int mi=0;mi<4;mi++){
                int row = wm*64 + mi*16 + tr;
                af[mi][0]=__float_as_uint(Ash[row  ][kk*8+tc  ]);
                af[mi][1]=__float_as_uint(Ash[row+8][kk*8+tc  ]);
                af[mi][2]=__float_as_uint(Ash[row  ][kk*8+tc+4]);
                af[mi][3]=__float_as_uint(Ash[row+8][kk*8+tc+4]);
            }
            #pragma unroll
            for (int ni=0;ni<4;ni++){
                int col = wn*32 + ni*8 + tr;
                bf[ni][0]=__float_as_uint(Bsh[col][kk*8+tc  ]);
                bf[ni][1]=__float_as_uint(Bsh[col][kk*8+tc+4]);
            }
            #pragma unroll
            for (int mi=0;mi<4;mi++)
                #pragma unroll
                for (int ni=0;ni<4;ni++)
                    MMA_TF32(acc[mi][ni], af[mi], bf[ni]);
        }
        __syncthreads();
    }

    #pragma unroll
    for (int mi=0;mi<4;mi++){
        size_t r1 = m0 + (size_t)(wm*64 + mi*16 + tr);
        size_t r2 = r1 + 8;
        #pragma unroll
        for (int ni=0;ni<4;ni++){
            int gcol = wn*32 + ni*8 + 2*tc;
            float b0 = bo[gcol], b1 = bo[gcol+1];
            float2 gt1 = *(const float2*)(g_gs + r1*CDIM + gcol);
            float2 gt2 = *(const float2*)(g_gs + r2*CDIM + gcol);
            *(float2*)(out + r1*CDIM + gcol) =
                make_float2(gt1.x*(acc[mi][ni][0]+b0), gt1.y*(acc[mi][ni][1]+b1));
            *(float2*)(out + r2*CDIM + gcol) =
                make_float2(gt2.x*(acc[mi][ni][2]+b0), gt2.y*(acc[mi][ni][3]+b1));
        }
    }
}

/* ------------------------------------------------------------------ */
extern "C" void kernel_launch(void* const* d_in, const int* in_sizes, int n_in,
                              void* d_out, int out_size)
{
    const float* z    = (const float*)d_in[0];
    const float* mask = (const float*)d_in[1];
    const float* lniw = (const float*)d_in[2];
    const float* lnib = (const float*)d_in[3];
    const float* wap  = (const float*)d_in[4];
    const float* bap  = (const float*)d_in[5];
    const float* wag  = (const float*)d_in[6];
    const float* bag  = (const float*)d_in[7];
    const float* wbp  = (const float*)d_in[8];
    const float* bbp  = (const float*)d_in[9];
    const float* wbg  = (const float*)d_in[10];
    const float* bbg  = (const float*)d_in[11];
    const float* wg   = (const float*)d_in[12];
    const float* bg   = (const float*)d_in[13];
    const float* lnow = (const float*)d_in[14];
    const float* lnob = (const float*)d_in[15];
    const float* wo   = (const float*)d_in[16];
    const float* bo   = (const float*)d_in[17];
    float* out = (float*)d_out;

    k_build<<<(CDIM*640 + 255)/256, 256>>>(wap,wag,wbp,wbg,wg,bap,bag,bbp,bbg,bg);
    k_ln_in<<<NROWS/8, 256>>>(z, lniw, lnib);
    dim3 g1(5, NROWS/128);
    k_gemm1<<<g1, 256>>>(mask);
    dim3 g2(NSEQ/128, NSEQ/128, CDIM);
    k_gemm2<<<g2, 256>>>();
    k_gather<<<NROWS/32, 256>>>(lnow, lnob);
    k_gemm3<<<NROWS/128, 256>>>(wo, bo, out);
}

// round 4
// speedup vs baseline: 1.3357x; 1.3357x over previous
#include <cuda_runtime.h>
#include <cstdint>

#define NSEQ   384
#define CDIM   128
#define NROWS  (NSEQ*NSEQ)          /* 147456 */
#define LN_EPS 1e-5f

/* ------------------------------------------------------------------ */
/* Scratch (device globals)                                            */
/* ------------------------------------------------------------------ */
__device__ float g_x [(size_t)NROWS*CDIM];   /* LN(z)                       */
__device__ float g_at[(size_t)CDIM*NROWS];   /* a, layout [c][i*N+k]        */
__device__ float g_bt[(size_t)CDIM*NROWS];   /* b, layout [c][j*N+k]        */
__device__ float g_gs[(size_t)NROWS*CDIM];   /* sigmoid(x@w_g+b_g), [r][c]  */
__device__ float g_tt[(size_t)CDIM*NROWS];   /* t, layout [c][i*N+j]        */
__device__ float g_y [(size_t)NROWS*CDIM];   /* LN_out(t), [r][c]           */
__device__ float g_wcat[640*CDIM];           /* weights transposed [n][k]   */
__device__ float g_wot[CDIM*CDIM];           /* w_o transposed [n][k]       */
__device__ float g_bcat[640];

__device__ __forceinline__ float sigm(float x){ return 1.f/(1.f+__expf(-x)); }
__device__ __forceinline__ float f2tf(float f){
    unsigned u; asm("cvt.rna.tf32.f32 %0, %1;" : "=r"(u) : "f"(f));
    return __uint_as_float(u);
}

#define MMA_TF32(d,a,b) asm volatile( \
    "mma.sync.aligned.m16n8k8.row.col.f32.tf32.tf32.f32 " \
    "{%0,%1,%2,%3},{%4,%5,%6,%7},{%8,%9},{%0,%1,%2,%3};" \
    : "+f"(d[0]),"+f"(d[1]),"+f"(d[2]),"+f"(d[3]) \
    : "r"(a[0]),"r"(a[1]),"r"(a[2]),"r"(a[3]),"r"(b[0]),"r"(b[1]))

/* ------------------------------------------------------------------ */
/* Shared mainloop: acc += A[128 x K] * B[128 x K]^T, tf32 mma.sync.   */
/* Stride-36 smem pad: fragment loads hit bank (4*tr + tc) -> all 32   */
/* banks distinct (33-pad of round 1 gave ~3-way conflicts).           */
/* Register-prefetch pipeline hides LDG latency across k-chunks.       */
/* ------------------------------------------------------------------ */
template<int KTOT>
__device__ __forceinline__ void mm_loop(const float* __restrict__ A, int lda,
                                        const float* __restrict__ B, int ldb,
                                        float (&Ash)[128][36], float (&Bsh)[128][36],
                                        float (&acc)[4][4][4])
{
    const int tid  = threadIdx.x;
    const int warp = tid>>5, lane = tid&31;
    const int wm = warp & 1, wn = warp >> 1;
    const int tr = lane>>2, tc = lane&3;
    const int row0 = tid>>3, c4 = tid&7;
    constexpr int NC = KTOT/32;

    float4 pa[4], pb[4];
    #pragma unroll
    for (int it=0; it<4; it++){
        pa[it] = *(const float4*)(A + (size_t)(row0+it*32)*lda + c4*4);
        pb[it] = *(const float4*)(B + (size_t)(row0+it*32)*ldb + c4*4);
    }

    for (int c=0; c<NC; c++){
        #pragma unroll
        for (int it=0; it<4; it++){
            int r = row0 + it*32;
            *(float4*)&Ash[r][c4*4] = make_float4(f2tf(pa[it].x), f2tf(pa[it].y),
                                                  f2tf(pa[it].z), f2tf(pa[it].w));
            *(float4*)&Bsh[r][c4*4] = make_float4(f2tf(pb[it].x), f2tf(pb[it].y),
                                                  f2tf(pb[it].z), f2tf(pb[it].w));
        }
        __syncthreads();

        if (c+1 < NC){
            const int k0 = (c+1)*32;
            #pragma unroll
            for (int it=0; it<4; it++){
                pa[it] = *(const float4*)(A + (size_t)(row0+it*32)*lda + k0 + c4*4);
                pb[it] = *(const float4*)(B + (size_t)(row0+it*32)*ldb + k0 + c4*4);
            }
        }

        #pragma unroll
        for (int kk=0; kk<4; kk++){
            unsigned af[4][4], bf[4][2];
            #pragma unroll
            for (int mi=0; mi<4; mi++){
                int row = wm*64 + mi*16 + tr;
                af[mi][0]=__float_as_uint(Ash[row  ][kk*8+tc  ]);
                af[mi][1]=__float_as_uint(Ash[row+8][kk*8+tc  ]);
                af[mi][2]=__float_as_uint(Ash[row  ][kk*8+tc+4]);
                af[mi][3]=__float_as_uint(Ash[row+8][kk*8+tc+4]);
            }
            #pragma unroll
            for (int ni=0; ni<4; ni++){
                int col = wn*32 + ni*8 + tr;
                bf[ni][0]=__float_as_uint(Bsh[col][kk*8+tc  ]);
                bf[ni][1]=__float_as_uint(Bsh[col][kk*8+tc+4]);
            }
            #pragma unroll
            for (int mi=0; mi<4; mi++)
                #pragma unroll
                for (int ni=0; ni<4; ni++)
                    MMA_TF32(acc[mi][ni], af[mi], bf[ni]);
        }
        __syncthreads();
    }
}

#define ACC_ZERO(acc) do { \
    _Pragma("unroll") \
    for (int _i=0;_i<4;_i++) \
        _Pragma("unroll") \
        for (int _j=0;_j<4;_j++) \
            _Pragma("unroll") \
            for (int _r=0;_r<4;_r++) acc[_i][_j][_r]=0.f; \
} while(0)

/* ------------------------------------------------------------------ */
/* K0: transposed weight concat [n][k] + biases + w_o^T                */
/* ------------------------------------------------------------------ */
__global__ void k_build(const float* __restrict__ wap, const float* __restrict__ wag,
                        const float* __restrict__ wbp, const float* __restrict__ wbg,
                        const float* __restrict__ wg,  const float* __restrict__ wo,
                        const float* __restrict__ bap, const float* __restrict__ bag,
                        const float* __restrict__ bbp, const float* __restrict__ bbg,
                        const float* __restrict__ bg)
{
    int id = blockIdx.x*blockDim.x + threadIdx.x;
    if (id < CDIM*640){
        int k = id/640, col = id%640;
        float v;
        if (col < 256)      { int t = col>>1;        v = (col&1) ? wag[k*CDIM+t] : wap[k*CDIM+t]; }
        else if (col < 512) { int t = (col-256)>>1;  v = (col&1) ? wbg[k*CDIM+t] : wbp[k*CDIM+t]; }
        else                {                        v = wg[k*CDIM + (col-512)]; }
        g_wcat[col*CDIM + k] = v;
        if (k == 0){
            float b;
            if (col < 256)      { int t = col>>1;       b = (col&1) ? bag[t] : bap[t]; }
            else if (col < 512) { int t = (col-256)>>1; b = (col&1) ? bbg[t] : bbp[t]; }
            else                {                       b = bg[col-512]; }
            g_bcat[col] = b;
        }
    } else {
        int id2 = id - CDIM*640;
        if (id2 < CDIM*CDIM){
            int n = id2 >> 7, k = id2 & 127;
            g_wot[n*CDIM + k] = wo[k*CDIM + n];
        }
    }
}

/* ------------------------------------------------------------------ */
/* K1: input LayerNorm, one warp per row                               */
/* ------------------------------------------------------------------ */
__global__ void k_ln_in(const float* __restrict__ z,
                        const float* __restrict__ w, const float* __restrict__ b)
{
    int warp = threadIdx.x>>5, lane = threadIdx.x&31;
    size_t row = (size_t)blockIdx.x*8 + warp;
    float4 v = ((const float4*)(z + row*CDIM))[lane];
    float s = v.x+v.y+v.z+v.w;
    #pragma unroll
    for (int o=16;o;o>>=1) s += __shfl_xor_sync(~0u, s, o);
    float mu = s*(1.f/128.f);
    float dx=v.x-mu, dy=v.y-mu, dz=v.z-mu, dw=v.w-mu;
    float q = dx*dx+dy*dy+dz*dz+dw*dw;
    #pragma unroll
    for (int o=16;o;o>>=1) q += __shfl_xor_sync(~0u, q, o);
    float rs = rsqrtf(q*(1.f/128.f) + LN_EPS);
    float4 wv = ((const float4*)w)[lane];
    float4 bv = ((const float4*)b)[lane];
    float4 o4;
    o4.x = dx*rs*wv.x + bv.x;  o4.y = dy*rs*wv.y + bv.y;
    o4.z = dz*rs*wv.z + bv.z;  o4.w = dw*rs*wv.w + bv.w;
    ((float4*)(g_x + row*CDIM))[lane] = o4;
}

/* ------------------------------------------------------------------ */
/* K2: projection GEMM + gated epilogue                                */
/* grid (5, 1152): x = n-block (128 of 640 cols), y = m strip          */
/* ------------------------------------------------------------------ */
__global__ __launch_bounds__(256) void k_gemm1(const float* __restrict__ mask)
{
    __shared__ float Ash[128][36];
    __shared__ float Bsh[128][36];
    const int nb = blockIdx.x;
    const size_t m0 = (size_t)blockIdx.y*128;
    const int n0 = nb*128;

    float acc[4][4][4];
    ACC_ZERO(acc);
    mm_loop<CDIM>(g_x + m0*CDIM, CDIM,
                  g_wcat + (size_t)n0*CDIM, CDIM, Ash, Bsh, acc);

    const int warp = threadIdx.x>>5, lane = threadIdx.x&31;
    const int wm = warp & 1, wn = warp >> 1;
    const int tr = lane>>2, tc = lane&3;

    #pragma unroll
    for (int mi=0;mi<4;mi++){
        size_t r1 = m0 + (size_t)(wm*64 + mi*16 + tr);
        size_t r2 = r1 + 8;
        float mk1 = mask[r1], mk2 = mask[r2];
        #pragma unroll
        for (int ni=0;ni<4;ni++){
            int gcol = n0 + wn*32 + ni*8 + 2*tc;
            float b0 = g_bcat[gcol], b1 = g_bcat[gcol+1];
            float c0 = acc[mi][ni][0]+b0, c1 = acc[mi][ni][1]+b1;
            float c2 = acc[mi][ni][2]+b0, c3 = acc[mi][ni][3]+b1;
            if (nb < 2){                       /* a = m*sig(g)*p, transposed */
                size_t ch = (size_t)(gcol>>1);
                g_at[ch*NROWS + r1] = mk1*sigm(c1)*c0;
                g_at[ch*NROWS + r2] = mk2*sigm(c3)*c2;
            } else if (nb < 4){
                size_t ch = (size_t)((gcol>>1) - 128);
                g_bt[ch*NROWS + r1] = mk1*sigm(c1)*c0;
                g_bt[ch*NROWS + r2] = mk2*sigm(c3)*c2;
            } else {                           /* gate, row-major */
                int gc = gcol - 512;
                g_gs[r1*CDIM+gc  ]=sigm(c0); g_gs[r1*CDIM+gc+1]=sigm(c1);
                g_gs[r2*CDIM+gc  ]=sigm(c2); g_gs[r2*CDIM+gc+1]=sigm(c3);
            }
        }
    }
}

/* ------------------------------------------------------------------ */
/* K3: channel-batched einsum  T_c = A_c @ B_c^T                       */
/* ------------------------------------------------------------------ */
__global__ __launch_bounds__(256) void k_gemm2()
{
    __shared__ float Ash[128][36];
    __shared__ float Bsh[128][36];
    const size_t plane = (size_t)blockIdx.z*NROWS;
    const int m0 = blockIdx.y*128, n0 = blockIdx.x*128;

    float acc[4][4][4];
    ACC_ZERO(acc);
    mm_loop<NSEQ>(g_at + plane + (size_t)m0*NSEQ, NSEQ,
                  g_bt + plane + (size_t)n0*NSEQ, NSEQ, Ash, Bsh, acc);

    const int warp = threadIdx.x>>5, lane = threadIdx.x&31;
    const int wm = warp & 1, wn = warp >> 1;
    const int tr = lane>>2, tc = lane&3;

    #pragma unroll
    for (int mi=0;mi<4;mi++){
        size_t i1 = (size_t)(m0 + wm*64 + mi*16 + tr);
        size_t i2 = i1 + 8;
        #pragma unroll
        for (int ni=0;ni<4;ni++){
            int j = n0 + wn*32 + ni*8 + 2*tc;
            *(float2*)(g_tt + plane + i1*NSEQ + j) = make_float2(acc[mi][ni][0], acc[mi][ni][1]);
            *(float2*)(g_tt + plane + i2*NSEQ + j) = make_float2(acc[mi][ni][2], acc[mi][ni][3]);
        }
    }
}

/* ------------------------------------------------------------------ */
/* K4: gather t over channel planes + output LayerNorm                 */
/* ------------------------------------------------------------------ */
__global__ void k_gather(const float* __restrict__ lw, const float* __restrict__ lb)
{
    __shared__ float sh[128][33];
    const int tid = threadIdx.x;
    const size_t r0 = (size_t)blockIdx.x*32;
    #pragma unroll
    for (int it=0;it<16;it++){
        int idx = it*256 + tid;
        int c = idx>>5, r = idx&31;
        sh[c][r] = g_tt[(size_t)c*NROWS + r0 + r];
    }
    __syncthreads();
    const int warp = tid>>5, lane = tid&31;
    #pragma unroll
    for (int rr=0;rr<4;rr++){
        int r = warp*4 + rr;
        float v0=sh[lane][r], v1=sh[lane+32][r], v2=sh[lane+64][r], v3=sh[lane+96][r];
        float s = v0+v1+v2+v3;
        #pragma unroll
        for (int o=16;o;o>>=1) s += __shfl_xor_sync(~0u, s, o);
        float mu = s*(1.f/128.f);
        float d0=v0-mu,d1=v1-mu,d2=v2-mu,d3=v3-mu;
        float q = d0*d0+d1*d1+d2*d2+d3*d3;
        #pragma unroll
        for (int o=16;o;o>>=1) q += __shfl_xor_sync(~0u, q, o);
        float rs = rsqrtf(q*(1.f/128.f) + LN_EPS);
        float* yr = g_y + (r0+r)*CDIM;
        yr[lane   ] = d0*rs*lw[lane   ] + lb[lane   ];
        yr[lane+32] = d1*rs*lw[lane+32] + lb[lane+32];
        yr[lane+64] = d2*rs*lw[lane+64] + lb[lane+64];
        yr[lane+96] = d3*rs*lw[lane+96] + lb[lane+96];
    }
}

/* ------------------------------------------------------------------ */
/* K5: output GEMM * gate                                              */
/* ------------------------------------------------------------------ */
__global__ __launch_bounds__(256) void k_gemm3(const float* __restrict__ bo,
                                               float* __restrict__ out)
{
    __shared__ float Ash[128][36];
    __shared__ float Bsh[128][36];
    const size_t m0 = (size_t)blockIdx.x*128;

    float acc[4][4][4];
    ACC_ZERO(acc);
    mm_loop<CDIM>(g_y + m0*CDIM, CDIM, g_wot, CDIM, Ash, Bsh, acc);

    const int warp = threadIdx.x>>5, lane = threadIdx.x&31;
    const int wm = warp & 1, wn = warp >> 1;
    const int tr = lane>>2, tc = lane&3;

    #pragma unroll
    for (int mi=0;mi<4;mi++){
        size_t r1 = m0 + (size_t)(wm*64 + mi*16 + tr);
        size_t r2 = r1 + 8;
        #pragma unroll
        for (int ni=0;ni<4;ni++){
            int gcol = wn*32 + ni*8 + 2*tc;
            float b0 = bo[gcol], b1 = bo[gcol+1];
            float2 gt1 = *(const float2*)(g_gs + r1*CDIM + gcol);
            float2 gt2 = *(const float2*)(g_gs + r2*CDIM + gcol);
            *(float2*)(out + r1*CDIM + gcol) =
                make_float2(gt1.x*(acc[mi][ni][0]+b0), gt1.y*(acc[mi][ni][1]+b1));
            *(float2*)(out + r2*CDIM + gcol) =
                make_float2(gt2.x*(acc[mi][ni][2]+b0), gt2.y*(acc[mi][ni][3]+b1));
        }
    }
}

/* ------------------------------------------------------------------ */
extern "C" void kernel_launch(void* const* d_in, const int* in_sizes, int n_in,
                              void* d_out, int out_size)
{
    const float* z    = (const float*)d_in[0];
    const float* mask = (const float*)d_in[1];
    const float* lniw = (const float*)d_in[2];
    const float* lnib = (const float*)d_in[3];
    const float* wap  = (const float*)d_in[4];
    const float* bap  = (const float*)d_in[5];
    const float* wag  = (const float*)d_in[6];
    const float* bag  = (const float*)d_in[7];
    const float* wbp  = (const float*)d_in[8];
    const float* bbp  = (const float*)d_in[9];
    const float* wbg  = (const float*)d_in[10];
    const float* bbg  = (const float*)d_in[11];
    const float* wg   = (const float*)d_in[12];
    const float* bg   = (const float*)d_in[13];
    const float* lnow = (const float*)d_in[14];
    const float* lnob = (const float*)d_in[15];
    const float* wo   = (const float*)d_in[16];
    const float* bo   = (const float*)d_in[17];
    float* out = (float*)d_out;

    k_build<<<(CDIM*640 + CDIM*CDIM + 255)/256, 256>>>(wap,wag,wbp,wbg,wg,wo,
                                                       bap,bag,bbp,bbg,bg);
    k_ln_in<<<NROWS/8, 256>>>(z, lniw, lnib);
    dim3 g1(5, NROWS/128);
    k_gemm1<<<g1, 256>>>(mask);
    dim3 g2(NSEQ/128, NSEQ/128, CDIM);
    k_gemm2<<<g2, 256>>>();
    k_gather<<<NROWS/32, 256>>>(lnow, lnob);
    k_gemm3<<<NROWS/128, 256>>>(bo, out);
}

// round 5
// speedup vs baseline: 1.4824x; 1.1098x over previous
#include <cuda_runtime.h>
#include <cstdint>

#define NSEQ   384
#define CDIM   128
#define NROWS  (NSEQ*NSEQ)          /* 147456 */
#define LN_EPS 1e-5f

/* ------------------------------------------------------------------ */
/* Scratch (device globals)                                            */
/* ------------------------------------------------------------------ */
__device__ float g_x [(size_t)NROWS*CDIM];   /* LN(z), tf32-rounded         */
__device__ float g_at[(size_t)CDIM*NROWS];   /* a, [c][i*N+k], tf32-rounded */
__device__ float g_bt[(size_t)CDIM*NROWS];   /* b, [c][j*N+k], tf32-rounded */
__device__ float g_gs[(size_t)NROWS*CDIM];   /* sigmoid gate, [r][c], f32   */
__device__ float g_tt[(size_t)CDIM*NROWS];   /* t, [c][i*N+j], f32          */
__device__ float g_y [(size_t)NROWS*CDIM];   /* LN_out(t), tf32-rounded     */
__device__ float g_wcat[640*CDIM];           /* weights [n][k], tf32        */
__device__ float g_wot[CDIM*CDIM];           /* w_o^T [n][k], tf32          */
__device__ float g_bcat[640];

__device__ __forceinline__ float sigm(float x){ return 1.f/(1.f+__expf(-x)); }
__device__ __forceinline__ float f2tf(float f){
    unsigned u; asm("cvt.rna.tf32.f32 %0, %1;" : "=r"(u) : "f"(f));
    return __uint_as_float(u);
}
__device__ __forceinline__ uint32_t smem_u32(const void* p){
    uint32_t a;
    asm("{ .reg .u64 t; cvta.to.shared.u64 t, %1; cvt.u32.u64 %0, t; }"
        : "=r"(a) : "l"(p));
    return a;
}

#define MMA_TF32(d,a,b) asm volatile( \
    "mma.sync.aligned.m16n8k8.row.col.f32.tf32.tf32.f32 " \
    "{%0,%1,%2,%3},{%4,%5,%6,%7},{%8,%9},{%0,%1,%2,%3};" \
    : "+f"(d[0]),"+f"(d[1]),"+f"(d[2]),"+f"(d[3]) \
    : "r"(a[0]),"r"(a[1]),"r"(a[2]),"r"(a[3]),"r"(b[0]),"r"(b[1]))

#define LDSM4(r0,r1,r2,r3,a) asm volatile( \
    "ldmatrix.sync.aligned.m8n8.x4.shared.b16 {%0,%1,%2,%3}, [%4];" \
    : "=r"(r0),"=r"(r1),"=r"(r2),"=r"(r3) : "r"(a))

#define CP16(dst,src) asm volatile( \
    "cp.async.cg.shared.global [%0], [%1], 16;" :: "r"(dst), "l"(src))
#define CP_COMMIT() asm volatile("cp.async.commit_group;" ::: "memory")
#define CP_WAIT1()  asm volatile("cp.async.wait_group 1;" ::: "memory")
#define CP_WAIT0()  asm volatile("cp.async.wait_group 0;" ::: "memory")

/* smem tile: BK=16, rows padded to 20 words (ldmatrix conflict-free:   */
/* bank(row) = 20*row mod 32 covers all 8 rows distinctly, 16B each)    */
#define PADK 20
#define STG  (128*PADK)              /* words per stage per matrix */

/* ------------------------------------------------------------------ */
/* mm_loop: acc[4][8][4] += A[128 x K] * B[128 x K]^T                   */
/* 128 threads, 4 warps (2x2), warp tile 64x64, cp.async double buffer, */
/* ldmatrix.x4 fragments. A,B must be pre-rounded to tf32 values.       */
/* ------------------------------------------------------------------ */
template<int KTOT>
__device__ __forceinline__ void mm_loop(const float* __restrict__ A, int lda,
                                        const float* __restrict__ B, int ldb,
                                        float* AshBase, float* BshBase,
                                        float (&acc)[4][8][4])
{
    const int tid  = threadIdx.x;
    const int warp = tid>>5, lane = tid&31;
    const int wm = warp>>1, wn = warp&1;
    constexpr int NC = KTOT/16;

    const uint32_t sA = smem_u32(AshBase);
    const uint32_t sB = smem_u32(BshBase);

    const int crow = tid>>2, cseg = tid&3;       /* copy mapping */
    const int ar  = lane & 15,          ac4 = (lane>>4)*4;           /* A lanes */
    const int br  = (lane&7)+((lane>>4)<<3), bc4 = ((lane>>3)&1)*4;  /* B lanes */

    /* prologue: chunk 0 -> buf 0 */
    #pragma unroll
    for (int it=0; it<4; it++){
        int row = crow + it*32;
        CP16(sA + (row*PADK + cseg*4)*4, A + (size_t)row*lda + cseg*4);
        CP16(sB + (row*PADK + cseg*4)*4, B + (size_t)row*ldb + cseg*4);
    }
    CP_COMMIT();

    for (int c=0; c<NC; c++){
        const int buf = c & 1;
        if (c+1 < NC){
            const int nbuf = (c+1)&1;
            const int k0 = (c+1)*16;
            #pragma unroll
            for (int it=0; it<4; it++){
                int row = crow + it*32;
                CP16(sA + (nbuf*STG + row*PADK + cseg*4)*4,
                     A + (size_t)row*lda + k0 + cseg*4);
                CP16(sB + (nbuf*STG + row*PADK + cseg*4)*4,
                     B + (size_t)row*ldb + k0 + cseg*4);
            }
            CP_COMMIT();
            CP_WAIT1();
        } else {
            CP_WAIT0();
        }
        __syncthreads();

        #pragma unroll
        for (int kk=0; kk<2; kk++){
            unsigned af[4][4], bf[4][4];
            #pragma unroll
            for (int mi=0; mi<4; mi++){
                uint32_t a = sA + (buf*STG + (wm*64 + mi*16 + ar)*PADK
                                   + kk*8 + ac4)*4;
                LDSM4(af[mi][0], af[mi][1], af[mi][2], af[mi][3], a);
            }
            #pragma unroll
            for (int p=0; p<4; p++){
                uint32_t a = sB + (buf*STG + (wn*64 + p*16 + br)*PADK
                                   + kk*8 + bc4)*4;
                LDSM4(bf[p][0], bf[p][1], bf[p][2], bf[p][3], a);
            }
            #pragma unroll
            for (int mi=0; mi<4; mi++)
                #pragma unroll
                for (int p=0; p<4; p++){
                    unsigned b0[2] = { bf[p][0], bf[p][1] };
                    unsigned b1[2] = { bf[p][2], bf[p][3] };
                    MMA_TF32(acc[mi][2*p  ], af[mi], b0);
                    MMA_TF32(acc[mi][2*p+1], af[mi], b1);
                }
        }
        __syncthreads();
    }
}

#define ACC_ZERO(acc) do { \
    _Pragma("unroll") \
    for (int _i=0;_i<4;_i++) \
        _Pragma("unroll") \
        for (int _j=0;_j<8;_j++) \
            _Pragma("unroll") \
            for (int _r=0;_r<4;_r++) acc[_i][_j][_r]=0.f; \
} while(0)

/* ------------------------------------------------------------------ */
/* K0: transposed tf32 weight concat [n][k] + biases + w_o^T           */
/* ------------------------------------------------------------------ */
__global__ void k_build(const float* __restrict__ wap, const float* __restrict__ wag,
                        const float* __restrict__ wbp, const float* __restrict__ wbg,
                        const float* __restrict__ wg,  const float* __restrict__ wo,
                        const float* __restrict__ bap, const float* __restrict__ bag,
                        const float* __restrict__ bbp, const float* __restrict__ bbg,
                        const float* __restrict__ bg)
{
    int id = blockIdx.x*blockDim.x + threadIdx.x;
    if (id < CDIM*640){
        int k = id/640, col = id%640;
        float v;
        if (col < 256)      { int t = col>>1;        v = (col&1) ? wag[k*CDIM+t] : wap[k*CDIM+t]; }
        else if (col < 512) { int t = (col-256)>>1;  v = (col&1) ? wbg[k*CDIM+t] : wbp[k*CDIM+t]; }
        else                {                        v = wg[k*CDIM + (col-512)]; }
        g_wcat[col*CDIM + k] = f2tf(v);
        if (k == 0){
            float b;
            if (col < 256)      { int t = col>>1;       b = (col&1) ? bag[t] : bap[t]; }
            else if (col < 512) { int t = (col-256)>>1; b = (col&1) ? bbg[t] : bbp[t]; }
            else                {                       b = bg[col-512]; }
            g_bcat[col] = b;
        }
    } else {
        int id2 = id - CDIM*640;
        if (id2 < CDIM*CDIM){
            int n = id2 >> 7, k = id2 & 127;
            g_wot[n*CDIM + k] = f2tf(wo[k*CDIM + n]);
        }
    }
}

/* ------------------------------------------------------------------ */
/* K1: input LayerNorm, one warp per row, tf32-rounded store           */
/* ------------------------------------------------------------------ */
__global__ void k_ln_in(const float* __restrict__ z,
                        const float* __restrict__ w, const float* __restrict__ b)
{
    int warp = threadIdx.x>>5, lane = threadIdx.x&31;
    size_t row = (size_t)blockIdx.x*8 + warp;
    float4 v = ((const float4*)(z + row*CDIM))[lane];
    float s = v.x+v.y+v.z+v.w;
    #pragma unroll
    for (int o=16;o;o>>=1) s += __shfl_xor_sync(~0u, s, o);
    float mu = s*(1.f/128.f);
    float dx=v.x-mu, dy=v.y-mu, dz=v.z-mu, dw=v.w-mu;
    float q = dx*dx+dy*dy+dz*dz+dw*dw;
    #pragma unroll
    for (int o=16;o;o>>=1) q += __shfl_xor_sync(~0u, q, o);
    float rs = rsqrtf(q*(1.f/128.f) + LN_EPS);
    float4 wv = ((const float4*)w)[lane];
    float4 bv = ((const float4*)b)[lane];
    float4 o4;
    o4.x = f2tf(dx*rs*wv.x + bv.x);  o4.y = f2tf(dy*rs*wv.y + bv.y);
    o4.z = f2tf(dz*rs*wv.z + bv.z);  o4.w = f2tf(dw*rs*wv.w + bv.w);
    ((float4*)(g_x + row*CDIM))[lane] = o4;
}

/* ------------------------------------------------------------------ */
/* K2: projection GEMM + gated epilogue. grid (5, 1152), 128 threads   */
/* ------------------------------------------------------------------ */
__global__ __launch_bounds__(128) void k_gemm1(const float* __restrict__ mask)
{
    __shared__ float Ash[2*STG];
    __shared__ float Bsh[2*STG];
    const int nb = blockIdx.x;
    const size_t m0 = (size_t)blockIdx.y*128;
    const int n0 = nb*128;

    float acc[4][8][4];
    ACC_ZERO(acc);
    mm_loop<CDIM>(g_x + m0*CDIM, CDIM,
                  g_wcat + (size_t)n0*CDIM, CDIM, Ash, Bsh, acc);

    const int warp = threadIdx.x>>5, lane = threadIdx.x&31;
    const int wm = warp>>1, wn = warp&1;
    const int tr = lane>>2, tc = lane&3;

    #pragma unroll
    for (int mi=0;mi<4;mi++){
        size_t r1 = m0 + (size_t)(wm*64 + mi*16 + tr);
        size_t r2 = r1 + 8;
        float mk1 = mask[r1], mk2 = mask[r2];
        #pragma unroll
        for (int ni=0;ni<8;ni++){
            int gcol = n0 + wn*64 + ni*8 + 2*tc;
            float b0 = g_bcat[gcol], b1 = g_bcat[gcol+1];
            float c0 = acc[mi][ni][0]+b0, c1 = acc[mi][ni][1]+b1;
            float c2 = acc[mi][ni][2]+b0, c3 = acc[mi][ni][3]+b1;
            if (nb < 2){                       /* a = m*sig(g)*p, transposed */
                size_t ch = (size_t)(gcol>>1);
                g_at[ch*NROWS + r1] = f2tf(mk1*sigm(c1)*c0);
                g_at[ch*NROWS + r2] = f2tf(mk2*sigm(c3)*c2);
            } else if (nb < 4){
                size_t ch = (size_t)((gcol>>1) - 128);
                g_bt[ch*NROWS + r1] = f2tf(mk1*sigm(c1)*c0);
                g_bt[ch*NROWS + r2] = f2tf(mk2*sigm(c3)*c2);
            } else {                           /* gate, row-major */
                int gc = gcol - 512;
                g_gs[r1*CDIM+gc  ]=sigm(c0); g_gs[r1*CDIM+gc+1]=sigm(c1);
                g_gs[r2*CDIM+gc  ]=sigm(c2); g_gs[r2*CDIM+gc+1]=sigm(c3);
            }
        }
    }
}

/* ------------------------------------------------------------------ */
/* K3: channel-batched einsum  T_c = A_c @ B_c^T. grid (3,3,128)       */
/* ------------------------------------------------------------------ */
__global__ __launch_bounds__(128) void k_gemm2()
{
    __shared__ float Ash[2*STG];
    __shared__ float Bsh[2*STG];
    const size_t plane = (size_t)blockIdx.z*NROWS;
    const int m0 = blockIdx.y*128, n0 = blockIdx.x*128;

    float acc[4][8][4];
    ACC_ZERO(acc);
    mm_loop<NSEQ>(g_at + plane + (size_t)m0*NSEQ, NSEQ,
                  g_bt + plane + (size_t)n0*NSEQ, NSEQ, Ash, Bsh, acc);

    const int warp = threadIdx.x>>5, lane = threadIdx.x&31;
    const int wm = warp>>1, wn = warp&1;
    const int tr = lane>>2, tc = lane&3;

    #pragma unroll
    for (int mi=0;mi<4;mi++){
        size_t i1 = (size_t)(m0 + wm*64 + mi*16 + tr);
        size_t i2 = i1 + 8;
        #pragma unroll
        for (int ni=0;ni<8;ni++){
            int j = n0 + wn*64 + ni*8 + 2*tc;
            *(float2*)(g_tt + plane + i1*NSEQ + j) = make_float2(acc[mi][ni][0], acc[mi][ni][1]);
            *(float2*)(g_tt + plane + i2*NSEQ + j) = make_float2(acc[mi][ni][2], acc[mi][ni][3]);
        }
    }
}

/* ------------------------------------------------------------------ */
/* K4: gather t over channel planes + output LayerNorm (tf32 store)    */
/* ------------------------------------------------------------------ */
__global__ void k_gather(const float* __restrict__ lw, const float* __restrict__ lb)
{
    __shared__ float sh[128][33];
    const int tid = threadIdx.x;
    const size_t r0 = (size_t)blockIdx.x*32;
    #pragma unroll
    for (int it=0;it<16;it++){
        int idx = it*256 + tid;
        int c = idx>>5, r = idx&31;
        sh[c][r] = g_tt[(size_t)c*NROWS + r0 + r];
    }
    __syncthreads();
    const int warp = tid>>5, lane = tid&31;
    #pragma unroll
    for (int rr=0;rr<4;rr++){
        int r = warp*4 + rr;
        float v0=sh[lane][r], v1=sh[lane+32][r], v2=sh[lane+64][r], v3=sh[lane+96][r];
        float s = v0+v1+v2+v3;
        #pragma unroll
        for (int o=16;o;o>>=1) s += __shfl_xor_sync(~0u, s, o);
        float mu = s*(1.f/128.f);
        float d0=v0-mu,d1=v1-mu,d2=v2-mu,d3=v3-mu;
        float q = d0*d0+d1*d1+d2*d2+d3*d3;
        #pragma unroll
        for (int o=16;o;o>>=1) q += __shfl_xor_sync(~0u, q, o);
        float rs = rsqrtf(q*(1.f/128.f) + LN_EPS);
        float* yr = g_y + (r0+r)*CDIM;
        yr[lane   ] = f2tf(d0*rs*lw[lane   ] + lb[lane   ]);
        yr[lane+32] = f2tf(d1*rs*lw[lane+32] + lb[lane+32]);
        yr[lane+64] = f2tf(d2*rs*lw[lane+64] + lb[lane+64]);
        yr[lane+96] = f2tf(d3*rs*lw[lane+96] + lb[lane+96]);
    }
}

/* ------------------------------------------------------------------ */
/* K5: output GEMM * gate. grid (1152), 128 threads                    */
/* ------------------------------------------------------------------ */
__global__ __launch_bounds__(128) void k_gemm3(const float* __restrict__ bo,
                                               float* __restrict__ out)
{
    __shared__ float Ash[2*STG];
    __shared__ float Bsh[2*STG];
    const size_t m0 = (size_t)blockIdx.x*128;

    float acc[4][8][4];
    ACC_ZERO(acc);
    mm_loop<CDIM>(g_y + m0*CDIM, CDIM, g_wot, CDIM, Ash, Bsh, acc);

    const int warp = threadIdx.x>>5, lane = threadIdx.x&31;
    const int wm = warp>>1, wn = warp&1;
    const int tr = lane>>2, tc = lane&3;

    #pragma unroll
    for (int mi=0;mi<4;mi++){
        size_t r1 = m0 + (size_t)(wm*64 + mi*16 + tr);
        size_t r2 = r1 + 8;
        #pragma unroll
        for (int ni=0;ni<8;ni++){
            int gcol = wn*64 + ni*8 + 2*tc;
            float b0 = bo[gcol], b1 = bo[gcol+1];
            float2 gt1 = *(const float2*)(g_gs + r1*CDIM + gcol);
            float2 gt2 = *(const float2*)(g_gs + r2*CDIM + gcol);
            *(float2*)(out + r1*CDIM + gcol) =
                make_float2(gt1.x*(acc[mi][ni][0]+b0), gt1.y*(acc[mi][ni][1]+b1));
            *(float2*)(out + r2*CDIM + gcol) =
                make_float2(gt2.x*(acc[mi][ni][2]+b0), gt2.y*(acc[mi][ni][3]+b1));
        }
    }
}

/* ------------------------------------------------------------------ */
extern "C" void kernel_launch(void* const* d_in, const int* in_sizes, int n_in,
                              void* d_out, int out_size)
{
    const float* z    = (const float*)d_in[0];
    const float* mask = (const float*)d_in[1];
    const float* lniw = (const float*)d_in[2];
    const float* lnib = (const float*)d_in[3];
    const float* wap  = (const float*)d_in[4];
    const float* bap  = (const float*)d_in[5];
    const float* wag  = (const float*)d_in[6];
    const float* bag  = (const float*)d_in[7];
    const float* wbp  = (const float*)d_in[8];
    const float* bbp  = (const float*)d_in[9];
    const float* wbg  = (const float*)d_in[10];
    const float* bbg  = (const float*)d_in[11];
    const float* wg   = (const float*)d_in[12];
    const float* bg   = (const float*)d_in[13];
    const float* lnow = (const float*)d_in[14];
    const float* lnob = (const float*)d_in[15];
    const float* wo   = (const float*)d_in[16];
    const float* bo   = (const float*)d_in[17];
    float* out = (float*)d_out;

    k_build<<<(CDIM*640 + CDIM*CDIM + 255)/256, 256>>>(wap,wag,wbp,wbg,wg,wo,
                                                       bap,bag,bbp,bbg,bg);
    k_ln_in<<<NROWS/8, 256>>>(z, lniw, lnib);
    dim3 g1(5, NROWS/128);
    k_gemm1<<<g1, 128>>>(mask);
    dim3 g2(NSEQ/128, NSEQ/128, CDIM);
    k_gemm2<<<g2, 128>>>();
    k_gather<<<NROWS/32, 256>>>(lnow, lnob);
    k_gemm3<<<NROWS/128, 128>>>(bo, out);
}

// round 7
// speedup vs baseline: 1.5509x; 1.0462x over previous
#include <cuda_runtime.h>
#include <cstdint>

#define NSEQ   384
#define CDIM   128
#define NROWS  (NSEQ*NSEQ)          /* 147456 */
#define LN_EPS 1e-5f

/* ------------------------------------------------------------------ */
/* Scratch (device globals)                                            */
/* ------------------------------------------------------------------ */
__device__ float g_x [(size_t)NROWS*CDIM];   /* LN(z), tf32-rounded         */
__device__ float g_at[(size_t)CDIM*NROWS];   /* a, [c][i*N+k], tf32-rounded */
__device__ float g_bt[(size_t)CDIM*NROWS];   /* b, [c][j*N+k], tf32-rounded */
__device__ float g_gs[(size_t)NROWS*CDIM];   /* sigmoid gate, [r][c], f32   */
__device__ float g_tt[(size_t)CDIM*NROWS];   /* t, [c][i*N+j], f32          */
__device__ float g_y [(size_t)NROWS*CDIM];   /* LN_out(t), tf32-rounded     */
__device__ float g_wcat[640*CDIM];           /* weights [n][k], tf32        */
__device__ float g_wot[CDIM*CDIM];           /* w_o^T [n][k], tf32          */
__device__ float g_bcat[640];

__device__ __forceinline__ float sigm(float x){ return 1.f/(1.f+__expf(-x)); }
__device__ __forceinline__ float f2tf(float f){
    unsigned u; asm("cvt.rna.tf32.f32 %0, %1;" : "=r"(u) : "f"(f));
    return __uint_as_float(u);
}
__device__ __forceinline__ uint32_t smem_u32(const void* p){
    uint32_t a;
    asm("{ .reg .u64 t; cvta.to.shared.u64 t, %1; cvt.u32.u64 %0, t; }"
        : "=r"(a) : "l"(p));
    return a;
}

#define MMA_TF32(d,a,b) asm volatile( \
    "mma.sync.aligned.m16n8k8.row.col.f32.tf32.tf32.f32 " \
    "{%0,%1,%2,%3},{%4,%5,%6,%7},{%8,%9},{%0,%1,%2,%3};" \
    : "+f"(d[0]),"+f"(d[1]),"+f"(d[2]),"+f"(d[3]) \
    : "r"(a[0]),"r"(a[1]),"r"(a[2]),"r"(a[3]),"r"(b[0]),"r"(b[1]))

#define LDSM4(r0,r1,r2,r3,a) asm volatile( \
    "ldmatrix.sync.aligned.m8n8.x4.shared.b16 {%0,%1,%2,%3}, [%4];" \
    : "=r"(r0),"=r"(r1),"=r"(r2),"=r"(r3) : "r"(a))

#define CP16(dst,src) asm volatile( \
    "cp.async.cg.shared.global [%0], [%1], 16;" :: "r"(dst), "l"(src))
#define CP_COMMIT() asm volatile("cp.async.commit_group;" ::: "memory")
#define CP_WAIT1()  asm volatile("cp.async.wait_group 1;" ::: "memory")
#define CP_WAIT0()  asm volatile("cp.async.wait_group 0;" ::: "memory")

/* smem tile: BK=16, rows padded to 20 words (ldmatrix conflict-free)   */
#define PADK 20
#define STG_B   10240                /* bytes per matrix per stage      */
#define STAGE_B 20480                /* bytes per stage (A + B)         */
#define NST     3
#define SMEM_MM (NST*STAGE_B)        /* 61440 bytes dynamic smem        */

/* issue one 16-wide k-chunk of A and B into given stage */
__device__ __forceinline__ void issue_chunk(uint32_t sbase, int stage,
                                            const float* __restrict__ A, int lda,
                                            const float* __restrict__ B, int ldb,
                                            int k0, int crow, int cseg)
{
    #pragma unroll
    for (int it=0; it<4; it++){
        int row = crow + it*32;
        uint32_t d = sbase + stage*STAGE_B + (row*PADK + cseg*4)*4;
        CP16(d,         A + (size_t)row*lda + k0 + cseg*4);
        CP16(d + STG_B, B + (size_t)row*ldb + k0 + cseg*4);
    }
    CP_COMMIT();
}

/* ------------------------------------------------------------------ */
/* mm_loop: acc[4][8][4] += A[128 x K] * B[128 x K]^T                   */
/* 128 threads, 4 warps (2x2), warp tile 64x64, 3-stage cp.async ring,  */
/* ldmatrix.x4 fragments. A,B must be pre-rounded to tf32 values.       */
/* ------------------------------------------------------------------ */
template<int KTOT>
__device__ __forceinline__ void mm_loop(const float* __restrict__ A, int lda,
                                        const float* __restrict__ B, int ldb,
                                        uint32_t sbase,
                                        float (&acc)[4][8][4])
{
    const int tid  = threadIdx.x;
    const int warp = tid>>5, lane = tid&31;
    const int wm = warp>>1, wn = warp&1;
    constexpr int NC = KTOT/16;

    const int crow = tid>>2, cseg = tid&3;       /* copy mapping */
    const int ar  = lane & 15,          ac4 = (lane>>4)*4;           /* A lanes */
    const int br  = (lane&7)+((lane>>4)<<3), bc4 = ((lane>>3)&1)*4;  /* B lanes */

    /* prologue: chunks 0,1 -> stages 0,1 */
    issue_chunk(sbase, 0, A, lda, B, ldb, 0,  crow, cseg);
    issue_chunk(sbase, 1, A, lda, B, ldb, 16, crow, cseg);

    int st = 0;
    for (int c=0; c<NC; c++){
        if (c < NC-1) CP_WAIT1(); else CP_WAIT0();
        __syncthreads();                 /* chunk c resident; stage (c+2)%3 free */

        if (c+2 < NC){
            int nst = st+2; if (nst >= NST) nst -= NST;
            issue_chunk(sbase, nst, A, lda, B, ldb, (c+2)*16, crow, cseg);
        }

        const uint32_t sA = sbase + st*STAGE_B;
        const uint32_t sB = sA + STG_B;
        #pragma unroll
        for (int kk=0; kk<2; kk++){
            unsigned af[4][4], bf[4][4];
            #pragma unroll
            for (int mi=0; mi<4; mi++){
                uint32_t a = sA + ((wm*64 + mi*16 + ar)*PADK + kk*8 + ac4)*4;
                LDSM4(af[mi][0], af[mi][1], af[mi][2], af[mi][3], a);
            }
            #pragma unroll
            for (int p=0; p<4; p++){
                uint32_t a = sB + ((wn*64 + p*16 + br)*PADK + kk*8 + bc4)*4;
                LDSM4(bf[p][0], bf[p][1], bf[p][2], bf[p][3], a);
            }
            #pragma unroll
            for (int mi=0; mi<4; mi++)
                #pragma unroll
                for (int p=0; p<4; p++){
                    unsigned b0[2] = { bf[p][0], bf[p][1] };
                    unsigned b1[2] = { bf[p][2], bf[p][3] };
                    MMA_TF32(acc[mi][2*p  ], af[mi], b0);
                    MMA_TF32(acc[mi][2*p+1], af[mi], b1);
                }
        }
        if (++st >= NST) st -= NST;
    }
}

#define ACC_ZERO(acc) do { \
    _Pragma("unroll") \
    for (int _i=0;_i<4;_i++) \
        _Pragma("unroll") \
        for (int _j=0;_j<8;_j++) \
            _Pragma("unroll") \
            for (int _r=0;_r<4;_r++) acc[_i][_j][_r]=0.f; \
} while(0)

/* ------------------------------------------------------------------ */
/* K0: transposed tf32 weight concat [n][k] + biases + w_o^T           */
/* ------------------------------------------------------------------ */
__global__ void k_build(const float* __restrict__ wap, const float* __restrict__ wag,
                        const float* __restrict__ wbp, const float* __restrict__ wbg,
                        const float* __restrict__ wg,  const float* __restrict__ wo,
                        const float* __restrict__ bap, const float* __restrict__ bag,
                        const float* __restrict__ bbp, const float* __restrict__ bbg,
                        const float* __restrict__ bg)
{
    int id = blockIdx.x*blockDim.x + threadIdx.x;
    if (id < CDIM*640){
        int k = id/640, col = id%640;
        float v;
        if (col < 256)      { int t = col>>1;        v = (col&1) ? wag[k*CDIM+t] : wap[k*CDIM+t]; }
        else if (col < 512) { int t = (col-256)>>1;  v = (col&1) ? wbg[k*CDIM+t] : wbp[k*CDIM+t]; }
        else                {                        v = wg[k*CDIM + (col-512)]; }
        g_wcat[col*CDIM + k] = f2tf(v);
        if (k == 0){
            float b;
            if (col < 256)      { int t = col>>1;       b = (col&1) ? bag[t] : bap[t]; }
            else if (col < 512) { int t = (col-256)>>1; b = (col&1) ? bbg[t] : bbp[t]; }
            else                {                       b = bg[col-512]; }
            g_bcat[col] = b;
        }
    } else {
        int id2 = id - CDIM*640;
        if (id2 < CDIM*CDIM){
            int n = id2 >> 7, k = id2 & 127;
            g_wot[n*CDIM + k] = f2tf(wo[k*CDIM + n]);
        }
    }
}

/* ------------------------------------------------------------------ */
/* K1: input LayerNorm, one warp per row, tf32-rounded store           */
/* ------------------------------------------------------------------ */
__global__ void k_ln_in(const float* __restrict__ z,
                        const float* __restrict__ w, const float* __restrict__ b)
{
    int warp = threadIdx.x>>5, lane = threadIdx.x&31;
    size_t row = (size_t)blockIdx.x*8 + warp;
    float4 v = ((const float4*)(z + row*CDIM))[lane];
    float s = v.x+v.y+v.z+v.w;
    #pragma unroll
    for (int o=16;o;o>>=1) s += __shfl_xor_sync(~0u, s, o);
    float mu = s*(1.f/128.f);
    float dx=v.x-mu, dy=v.y-mu, dz=v.z-mu, dw=v.w-mu;
    float q = dx*dx+dy*dy+dz*dz+dw*dw;
    #pragma unroll
    for (int o=16;o;o>>=1) q += __shfl_xor_sync(~0u, q, o);
    float rs = rsqrtf(q*(1.f/128.f) + LN_EPS);
    float4 wv = ((const float4*)w)[lane];
    float4 bv = ((const float4*)b)[lane];
    float4 o4;
    o4.x = f2tf(dx*rs*wv.x + bv.x);  o4.y = f2tf(dy*rs*wv.y + bv.y);
    o4.z = f2tf(dz*rs*wv.z + bv.z);  o4.w = f2tf(dw*rs*wv.w + bv.w);
    ((float4*)(g_x + row*CDIM))[lane] = o4;
}

/* ------------------------------------------------------------------ */
/* K2: projection GEMM + gated epilogue. grid (5, 1152), 128 threads   */
/* a/b outputs staged through smem -> coalesced float4 channel runs    */
/* ------------------------------------------------------------------ */
__global__ __launch_bounds__(128) void k_gemm1(const float* __restrict__ mask)
{
    extern __shared__ float dynsm[];
    const uint32_t sbase = smem_u32(dynsm);
    const int nb = blockIdx.x;
    const size_t m0 = (size_t)blockIdx.y*128;
    const int n0 = nb*128;

    float acc[4][8][4];
    ACC_ZERO(acc);
    mm_loop<CDIM>(g_x + m0*CDIM, CDIM,
                  g_wcat + (size_t)n0*CDIM, CDIM, sbase, acc);

    const int tid = threadIdx.x;
    const int warp = tid>>5, lane = tid&31;
    const int wm = warp>>1, wn = warp&1;
    const int tr = lane>>2, tc = lane&3;

    if (nb < 4){
        __syncthreads();     /* reuse pipeline smem as [64][132] transpose buf */
        #pragma unroll
        for (int mi=0;mi<4;mi++){
            int rl = wm*64 + mi*16 + tr;
            size_t r1 = m0 + rl;
            float mk1 = mask[r1], mk2 = mask[r1+8];
            #pragma unroll
            for (int ni=0;ni<8;ni++){
                int gcol = n0 + wn*64 + ni*8 + 2*tc;
                int chl  = wn*32 + ni*4 + tc;
                float b0 = g_bcat[gcol], b1 = g_bcat[gcol+1];
                float c0 = acc[mi][ni][0]+b0, c1 = acc[mi][ni][1]+b1;
                float c2 = acc[mi][ni][2]+b0, c3 = acc[mi][ni][3]+b1;
                dynsm[chl*132 + rl    ] = f2tf(mk1*sigm(c1)*c0);
                dynsm[chl*132 + rl + 8] = f2tf(mk2*sigm(c3)*c2);
            }
        }
        __syncthreads();
        float* dst = (nb < 2) ? g_at : g_bt;
        const int chb = (nb&1)*64;
        const int chl = tid>>1, half = tid&1;
        float* drow = dst + (size_t)(chb+chl)*NROWS + m0 + half*64;
        const float* srow = dynsm + chl*132 + half*64;
        #pragma unroll
        for (int v2=0; v2<16; v2++)
            *(float4*)(drow + v2*4) = *(const float4*)(srow + v2*4);
    } else {
        #pragma unroll
        for (int mi=0;mi<4;mi++){
            size_t r1 = m0 + (size_t)(wm*64 + mi*16 + tr);
            size_t r2 = r1 + 8;
            #pragma unroll
            for (int ni=0;ni<8;ni++){
                int gcol = n0 + wn*64 + ni*8 + 2*tc;
                float b0 = g_bcat[gcol], b1 = g_bcat[gcol+1];
                int gc = gcol - 512;
                g_gs[r1*CDIM+gc  ]=sigm(acc[mi][ni][0]+b0);
                g_gs[r1*CDIM+gc+1]=sigm(acc[mi][ni][1]+b1);
                g_gs[r2*CDIM+gc  ]=sigm(acc[mi][ni][2]+b0);
                g_gs[r2*CDIM+gc+1]=sigm(acc[mi][ni][3]+b1);
            }
        }
    }
}

/* ------------------------------------------------------------------ */
/* K3: channel-batched einsum  T_c = A_c @ B_c^T. grid (3,3,128)       */
/* ------------------------------------------------------------------ */
__global__ __launch_bounds__(128) void k_gemm2()
{
    extern __shared__ float dynsm[];
    const uint32_t sbase = smem_u32(dynsm);
    const size_t plane = (size_t)blockIdx.z*NROWS;
    const int m0 = blockIdx.y*128, n0 = blockIdx.x*128;

    float acc[4][8][4];
    ACC_ZERO(acc);
    mm_loop<NSEQ>(g_at + plane + (size_t)m0*NSEQ, NSEQ,
                  g_bt + plane + (size_t)n0*NSEQ, NSEQ, sbase, acc);

    const int warp = threadIdx.x>>5, lane = threadIdx.x&31;
    const int wm = warp>>1, wn = warp&1;
    const int tr = lane>>2, tc = lane&3;

    #pragma unroll
    for (int mi=0;mi<4;mi++){
        size_t i1 = (size_t)(m0 + wm*64 + mi*16 + tr);
        size_t i2 = i1 + 8;
        #pragma unroll
        for (int ni=0;ni<8;ni++){
            int j = n0 + wn*64 + ni*8 + 2*tc;
            *(float2*)(g_tt + plane + i1*NSEQ + j) = make_float2(acc[mi][ni][0], acc[mi][ni][1]);
            *(float2*)(g_tt + plane + i2*NSEQ + j) = make_float2(acc[mi][ni][2], acc[mi][ni][3]);
        }
    }
}

/* ------------------------------------------------------------------ */
/* K4: gather t over channel planes + output LayerNorm (tf32 store)    */
/* ------------------------------------------------------------------ */
__global__ void k_gather(const float* __restrict__ lw, const float* __restrict__ lb)
{
    __shared__ float sh[128][33];
    const int tid = threadIdx.x;
    const size_t r0 = (size_t)blockIdx.x*32;
    #pragma unroll
    for (int it=0;it<16;it++){
        int idx = it*256 + tid;
        int c = idx>>5, r = idx&31;
        sh[c][r] = g_tt[(size_t)c*NROWS + r0 + r];
    }
    __syncthreads();
    const int warp = tid>>5, lane = tid&31;
    #pragma unroll
    for (int rr=0;rr<4;rr++){
        int r = warp*4 + rr;
        float v0=sh[lane][r], v1=sh[lane+32][r], v2=sh[lane+64][r], v3=sh[lane+96][r];
        float s = v0+v1+v2+v3;
        #pragma unroll
        for (int o=16;o;o>>=1) s += __shfl_xor_sync(~0u, s, o);
        float mu = s*(1.f/128.f);
        float d0=v0-mu,d1=v1-mu,d2=v2-mu,d3=v3-mu;
        float q = d0*d0+d1*d1+d2*d2+d3*d3;
        #pragma unroll
        for (int o=16;o;o>>=1) q += __shfl_xor_sync(~0u, q, o);
        float rs = rsqrtf(q*(1.f/128.f) + LN_EPS);
        float* yr = g_y + (r0+r)*CDIM;
        yr[lane   ] = f2tf(d0*rs*lw[lane   ] + lb[lane   ]);
        yr[lane+32] = f2tf(d1*rs*lw[lane+32] + lb[lane+32]);
        yr[lane+64] = f2tf(d2*rs*lw[lane+64] + lb[lane+64]);
        yr[lane+96] = f2tf(d3*rs*lw[lane+96] + lb[lane+96]);
    }
}

/* ------------------------------------------------------------------ */
/* K5: output GEMM * gate. grid (1152), 128 threads                    */
/* ------------------------------------------------------------------ */
__global__ __launch_bounds__(128) void k_gemm3(const float* __restrict__ bo,
                                               float* __restrict__ out)
{
    extern __shared__ float dynsm[];
    const uint32_t sbase = smem_u32(dynsm);
    const size_t m0 = (size_t)blockIdx.x*128;

    float acc[4][8][4];
    ACC_ZERO(acc);
    mm_loop<CDIM>(g_y + m0*CDIM, CDIM, g_wot, CDIM, sbase, acc);

    const int warp = threadIdx.x>>5, lane = threadIdx.x&31;
    const int wm = warp>>1, wn = warp&1;
    const int tr = lane>>2, tc = lane&3;

    #pragma unroll
    for (int mi=0;mi<4;mi++){
        size_t r1 = m0 + (size_t)(wm*64 + mi*16 + tr);
        size_t r2 = r1 + 8;
        #pragma unroll
        for (int ni=0;ni<8;ni++){
            int gcol = wn*64 + ni*8 + 2*tc;
            float b0 = bo[gcol], b1 = bo[gcol+1];
            float2 gt1 = *(const float2*)(g_gs + r1*CDIM + gcol);
            float2 gt2 = *(const float2*)(g_gs + r2*CDIM + gcol);
            *(float2*)(out + r1*CDIM + gcol) =
                make_float2(gt1.x*(acc[mi][ni][0]+b0), gt1.y*(acc[mi][ni][1]+b1));
            *(float2*)(out + r2*CDIM + gcol) =
                make_float2(gt2.x*(acc[mi][ni][2]+b0), gt2.y*(acc[mi][ni][3]+b1));
        }
    }
}

/* ------------------------------------------------------------------ */
extern "C" void kernel_launch(void* const* d_in, const int* in_sizes, int n_in,
                              void* d_out, int out_size)
{
    const float* z    = (const float*)d_in[0];
    const float* mask = (const float*)d_in[1];
    const float* lniw = (const float*)d_in[2];
    const float* lnib = (const float*)d_in[3];
    const float* wap  = (const float*)d_in[4];
    const float* bap  = (const float*)d_in[5];
    const float* wag  = (const float*)d_in[6];
    const float* bag  = (const float*)d_in[7];
    const float* wbp  = (const float*)d_in[8];
    const float* bbp  = (const float*)d_in[9];
    const float* wbg  = (const float*)d_in[10];
    const float* bbg  = (const float*)d_in[11];
    const float* wg   = (const float*)d_in[12];
    const float* bg   = (const float*)d_in[13];
    const float* lnow = (const float*)d_in[14];
    const float* lnob = (const float*)d_in[15];
    const float* wo   = (const float*)d_in[16];
    const float* bo   = (const float*)d_in[17];
    float* out = (float*)d_out;

    /* unconditional (deterministic, idempotent) — no static guards */
    cudaFuncSetAttribute(k_gemm1, cudaFuncAttributeMaxDynamicSharedMemorySize, SMEM_MM);
    cudaFuncSetAttribute(k_gemm2, cudaFuncAttributeMaxDynamicSharedMemorySize, SMEM_MM);
    cudaFuncSetAttribute(k_gemm3, cudaFuncAttributeMaxDynamicSharedMemorySize, SMEM_MM);

    k_build<<<(CDIM*640 + CDIM*CDIM + 255)/256, 256>>>(wap,wag,wbp,wbg,wg,wo,
                                                       bap,bag,bbp,bbg,bg);
    k_ln_in<<<NROWS/8, 256>>>(z, lniw, lnib);
    dim3 g1(5, NROWS/128);
    k_gemm1<<<g1, 128, SMEM_MM>>>(mask);
    dim3 g2(NSEQ/128, NSEQ/128, CDIM);
    k_gemm2<<<g2, 128, SMEM_MM>>>();
    k_gather<<<NROWS/32, 256>>>(lnow, lnob);
    k_gemm3<<<NROWS/128, 128, SMEM_MM>>>(bo, out);
}